// round 7
// baseline (speedup 1.0000x reference)
#include <cuda_runtime.h>
#include <math.h>

#define BS 2
#define CH 100
#define T 100
#define D 50
#define KNN 3
#define RES_INNER 12
#define RES_CTX 16
#define RES_TOT 28
#define DT 5000
#define OUT_C_STRIDE 140000
#define NT_TILES 5
#define TILE_ELEMS 1000            // 5 x 1000 = 5000 exactly; 250 active threads x 4

#define CSPLIT_IN 10
#define CPB_IN 10
#define CSPLIT_CTX 5
#define CPB_CTX 20

#define KNN_GRID   (BS * T)                                      // 200
#define INNER_GRID (BS * RES_INNER * NT_TILES * CSPLIT_IN)       // 1200
#define CTX_GRID   (BS * RES_CTX * NT_TILES * CSPLIT_CTX)        // 800
#define TOTAL_GRID (KNN_GRID + INNER_GRID + CTX_GRID)            // 2200

__device__ float g_ctx[BS * T * KNN];
__device__ unsigned g_done = 0;   // kNN blocks finished
__device__ unsigned g_exit = 0;   // ctx blocks finished (counter reset)

// ---------------- kNN body: one block per (b,t); 256 thr, 2-way channel split ----------------
__device__ void knn_body(const float* __restrict__ x, int bt) {
    const int b = bt / T, t = bt % T;
    const int tid = threadIdx.x;
    const int q = tid >> 7;
    const int s = tid & 127;

    __shared__ float sh_dot[2][T], sh_x3[2][T], sh_cs[2][T];
    __shared__ float sh_pd[T], sh_colsum[T], sh_xxt;

    const float* xb = x + (size_t)b * CH * T;

    if (s < T) {
        const int c0 = q * 50;
        float dot = 0.f, x3 = 0.f, cs = 0.f;
        #pragma unroll 5
        for (int c = c0; c < c0 + 50; ++c) {
            float xs = xb[c * T + s];
            float xt = xb[c * T + t];
            dot = fmaf(xt, xs, dot);
            x3  = fmaf(xs * xs, xs, x3);
            cs += xs;
        }
        sh_dot[q][s] = dot; sh_x3[q][s] = x3; sh_cs[q][s] = cs;
    }
    __syncthreads();

    if (tid < T) {
        float dot = sh_dot[0][tid] + sh_dot[1][tid];
        float x3  = sh_x3[0][tid]  + sh_x3[1][tid];
        sh_colsum[tid] = sh_cs[0][tid] + sh_cs[1][tid];
        if (tid == t) sh_xxt = x3;
        sh_pd[tid] = 2.0f * dot - x3;
    }
    __syncthreads();
    if (tid < T) sh_pd[tid] -= sh_xxt;
    __syncthreads();

    if (tid < 32) {
        #pragma unroll
        for (int k = 0; k < KNN; ++k) {
            float bv = -INFINITY; int bi = T;
            #pragma unroll
            for (int i = tid; i < T; i += 32) {
                float v = sh_pd[i];
                if (v > bv) { bv = v; bi = i; }
            }
            #pragma unroll
            for (int off = 16; off > 0; off >>= 1) {
                float ov = __shfl_down_sync(0xffffffffu, bv, off);
                int   oi = __shfl_down_sync(0xffffffffu, bi, off);
                if (ov > bv || (ov == bv && oi < bi)) { bv = ov; bi = oi; }
            }
            bi = __shfl_sync(0xffffffffu, bi, 0);
            if (tid == 0) {
                g_ctx[(b * T + t) * KNN + k] = sh_colsum[bi] / (float)CH;
                sh_pd[bi] = -INFINITY;
            }
            __syncwarp();
        }
        if (tid == 0) {
            __threadfence();
            atomicAdd(&g_done, 1u);
        }
    }
}

// ---------------- inner align body (r < 12): smem-staged x, LDS gathers ----------------
__device__ void inner_body(const float* __restrict__ x, float* __restrict__ out, int blk) {
    int cblk = blk % CSPLIT_IN;  blk /= CSPLIT_IN;
    int tile = blk % NT_TILES;   blk /= NT_TILES;
    int r    = blk % RES_INNER;
    int b    = blk / RES_INNER;
    const int tid = threadIdx.x;
    const int c0 = cblk * CPB_IN;

    __shared__ float smx[CPB_IN * T];    // 10 channels x 100 = 4KB, contiguous in x

    {
        const float* src = x + ((size_t)b * CH + c0) * T;
        for (int i = tid; i < CPB_IN * T; i += 256) smx[i] = src[i];
    }
    __syncthreads();

    if (tid >= 250) return;

    int   lo[4], hi[4];
    float wlo[4], whi[4];

    #pragma unroll
    for (int j = 0; j < 4; ++j) {
        int dt = tile * TILE_ELEMS + j * 250 + tid;   // lanes consecutive
        int d  = dt / T;
        int t  = dt - d * T;
        bool va     = (t + d) < T;
        float cl    = (float)(d + 1);
        float start = va ? ((float)t - cl * 0.5f) : 0.0f;
        float end   = va ? ((float)(t + d) + cl * 0.5f) : 0.0f;
        float binw  = __fdiv_rn(end - start, (float)RES_INNER);
        float coord = __fadd_rn(start, __fmul_rn((float)r + 0.5f, binw));
        bool valid  = (coord >= -1.0f) && (coord <= (float)T);
        float lof   = floorf(coord);
        float frac  = coord - lof;
        int loi = (int)lof;
        loi = loi < 0 ? 0 : (loi > T - 1 ? T - 1 : loi);
        int hii = loi + 1 > T - 1 ? T - 1 : loi + 1;
        lo[j] = loi; hi[j] = hii;
        wlo[j] = valid ? (1.0f - frac) : 0.0f;
        whi[j] = valid ? frac : 0.0f;
    }

    int outbase = ((b * CH + c0) * RES_TOT + r) * DT + tile * TILE_ELEMS + tid;

    #pragma unroll
    for (int c = 0; c < CPB_IN; ++c) {
        const float* bp = smx + c * T;
        #pragma unroll
        for (int j = 0; j < 4; ++j) {
            out[outbase + j * 250] = fmaf(whi[j], bp[hi[j]], wlo[j] * bp[lo[j]]);
        }
        outbase += OUT_C_STRIDE;
    }
}

// ---------------- ctx align body (r >= 12): 3-coeff precompute, STG.128 ----------------
__device__ void ctx_body(float* __restrict__ out, int blk) {
    int cblk = blk % CSPLIT_CTX;  blk /= CSPLIT_CTX;
    int tile = blk % NT_TILES;    blk /= NT_TILES;
    int rr   = blk % RES_CTX;
    int b    = blk / RES_CTX;

    // wait for kNN blocks (IDs 0..199, guaranteed wave-1 resident at 8 blocks/SM)
    if (threadIdx.x == 0) {
        while (atomicAdd(&g_done, 0u) < (unsigned)KNN_GRID) { __nanosleep(64); }
        __threadfence();
    }
    __syncthreads();

    if (threadIdx.x < 250) {
        int dt0 = tile * TILE_ELEMS + threadIdx.x * 4;   // 4 consecutive dt, 16B aligned
        float a0[4], a1[4], a2[4];

        #pragma unroll
        for (int j = 0; j < 4; ++j) {
            int dt = dt0 + j;
            int d  = dt / T;
            int t  = dt - d * T;
            bool va     = (t + d) < T;
            float cl    = (float)(d + 1);
            float start = va ? ((float)t - cl * 0.5f) : 0.0f;
            float end   = va ? ((float)(t + d) + cl * 0.5f) : 0.0f;
            float binw  = (end - start) * 0.0625f;   // /16 exact
            float coord = __fadd_rn(start, __fmul_rn((float)rr + 0.5f, binw));
            bool valid  = (coord >= -1.0f) && (coord <= (float)KNN);
            float lof   = floorf(coord);
            float frac  = coord - lof;
            int loi = (int)lof;
            loi = loi < 0 ? 0 : (loi > KNN - 1 ? KNN - 1 : loi);
            int hii = loi + 1 > KNN - 1 ? KNN - 1 : loi + 1;
            float wlo = valid ? (1.0f - frac) : 0.0f;
            float whi = valid ? frac : 0.0f;
            float c0a = 0.f, c1a = 0.f, c2a = 0.f;
            if (loi == 0) c0a += wlo; else if (loi == 1) c1a += wlo; else c2a += wlo;
            if (hii == 0) c0a += whi; else if (hii == 1) c1a += whi; else c2a += whi;
            a0[j] = c0a; a1[j] = c1a; a2[j] = c2a;
        }

        const int c0 = cblk * CPB_CTX;
        const float* cr = g_ctx + (b * CH + c0) * KNN;
        int outbase = ((b * CH + c0) * RES_TOT + (RES_INNER + rr)) * DT + dt0;

        #pragma unroll 4
        for (int c = 0; c < CPB_CTX; ++c) {
            float g0 = cr[0], g1 = cr[1], g2 = cr[2];
            float4 v;
            v.x = fmaf(a2[0], g2, fmaf(a1[0], g1, a0[0] * g0));
            v.y = fmaf(a2[1], g2, fmaf(a1[1], g1, a0[1] * g0));
            v.z = fmaf(a2[2], g2, fmaf(a1[2], g1, a0[2] * g0));
            v.w = fmaf(a2[3], g2, fmaf(a1[3], g1, a0[3] * g0));
            *reinterpret_cast<float4*>(out + outbase) = v;
            cr += KNN;
            outbase += OUT_C_STRIDE;
        }
    }

    __syncthreads();
    if (threadIdx.x == 0) {
        unsigned v = atomicAdd(&g_exit, 1u);
        if (v == (unsigned)(CTX_GRID - 1)) {
            g_done = 0;
            g_exit = 0;
            __threadfence();
        }
    }
}

// ---------------- fused kernel, 8 blocks/SM forced ----------------
__global__ void __launch_bounds__(256, 8)
graph_align_fused(const float* __restrict__ x, float* __restrict__ out) {
    unsigned bid = blockIdx.x;
    if (bid < KNN_GRID) {
        knn_body(x, (int)bid);
    } else if (bid < KNN_GRID + INNER_GRID) {
        inner_body(x, out, (int)(bid - KNN_GRID));
    } else {
        ctx_body(out, (int)(bid - KNN_GRID - INNER_GRID));
    }
}

extern "C" void kernel_launch(void* const* d_in, const int* in_sizes, int n_in,
                              void* d_out, int out_size) {
    const float* x = (const float*)d_in[0];
    float* out = (float*)d_out;
    graph_align_fused<<<TOTAL_GRID, 256>>>(x, out);
}

// round 8
// speedup vs baseline: 1.2164x; 1.2164x over previous
#include <cuda_runtime.h>
#include <math.h>
#include <stdint.h>

#define BS 2
#define CH 100
#define T 100
#define KNN 3
#define RES_INNER 12
#define RES_CTX 16
#define RES_TOT 28
#define DT 5000
#define OUT_C_STRIDE 140000
#define NT_TILES 5            // tiles of 1024 (last = 904)

#define CSPLIT_IN 10
#define CPB_IN 10
#define CSPLIT_CTX 5
#define CPB_CTX 20

#define KNN_GRID   (BS * T)                                   // 200
#define INNER_GRID (BS * RES_INNER * NT_TILES * CSPLIT_IN)    // 1200
#define CTX_GRID   (BS * RES_CTX * NT_TILES * CSPLIT_CTX)     // 800
#define TOTAL_GRID (KNN_GRID + INNER_GRID + CTX_GRID)         // 2200

__device__ float g_ctx[BS * T * KNN];
__device__ unsigned g_done = 0;
__device__ unsigned g_exit = 0;

// ---------------- TMA bulk-store helpers ----------------
__device__ __forceinline__ uint32_t smem_u32(const void* p) {
    uint32_t a;
    asm("{ .reg .u64 t; cvta.to.shared.u64 t, %1; cvt.u32.u64 %0, t; }" : "=r"(a) : "l"(p));
    return a;
}
__device__ __forceinline__ void bulk_store(void* gdst, uint32_t ssrc, uint32_t bytes) {
    asm volatile("cp.async.bulk.global.shared::cta.bulk_group [%0], [%1], %2;"
                 :: "l"(gdst), "r"(ssrc), "r"(bytes) : "memory");
}
__device__ __forceinline__ void bulk_commit() {
    asm volatile("cp.async.bulk.commit_group;" ::: "memory");
}
__device__ __forceinline__ void bulk_wait_read1() {
    asm volatile("cp.async.bulk.wait_group.read 1;" ::: "memory");
}
__device__ __forceinline__ void bulk_wait_all() {
    asm volatile("cp.async.bulk.wait_group 0;" ::: "memory");
}
__device__ __forceinline__ void fence_async_proxy() {
    asm volatile("fence.proxy.async.shared::cta;" ::: "memory");
}

// ---------------- shared storage union ----------------
struct KnnSh {
    float dot[2][T], x3[2][T], cs[2][T];
    float pd[T], colsum[T], xxt;
};
struct StoreSh {
    float obuf[2][1024];
    float g[CPB_CTX * KNN + 4];
};
union Sh { KnnSh k; StoreSh s; };

// ---------------- kNN body (unchanged from R6) ----------------
__device__ void knn_body(const float* __restrict__ x, int bt, KnnSh& sh) {
    const int b = bt / T, t = bt % T;
    const int tid = threadIdx.x;
    const int q = tid >> 7;
    const int s = tid & 127;

    const float* xb = x + (size_t)b * CH * T;

    if (s < T) {
        const int c0 = q * 50;
        float dot = 0.f, x3 = 0.f, cs = 0.f;
        #pragma unroll 5
        for (int c = c0; c < c0 + 50; ++c) {
            float xs = xb[c * T + s];
            float xt = xb[c * T + t];
            dot = fmaf(xt, xs, dot);
            x3  = fmaf(xs * xs, xs, x3);
            cs += xs;
        }
        sh.dot[q][s] = dot; sh.x3[q][s] = x3; sh.cs[q][s] = cs;
    }
    __syncthreads();

    if (tid < T) {
        float dot = sh.dot[0][tid] + sh.dot[1][tid];
        float x3  = sh.x3[0][tid]  + sh.x3[1][tid];
        sh.colsum[tid] = sh.cs[0][tid] + sh.cs[1][tid];
        if (tid == t) sh.xxt = x3;
        sh.pd[tid] = 2.0f * dot - x3;
    }
    __syncthreads();
    if (tid < T) sh.pd[tid] -= sh.xxt;
    __syncthreads();

    if (tid < 32) {
        #pragma unroll
        for (int k = 0; k < KNN; ++k) {
            float bv = -INFINITY; int bi = T;
            #pragma unroll
            for (int i = tid; i < T; i += 32) {
                float v = sh.pd[i];
                if (v > bv) { bv = v; bi = i; }
            }
            #pragma unroll
            for (int off = 16; off > 0; off >>= 1) {
                float ov = __shfl_down_sync(0xffffffffu, bv, off);
                int   oi = __shfl_down_sync(0xffffffffu, bi, off);
                if (ov > bv || (ov == bv && oi < bi)) { bv = ov; bi = oi; }
            }
            bi = __shfl_sync(0xffffffffu, bi, 0);
            if (tid == 0) {
                g_ctx[(b * T + t) * KNN + k] = sh.colsum[bi] / (float)CH;
                sh.pd[bi] = -INFINITY;
            }
            __syncwarp();
        }
        if (tid == 0) {
            __threadfence();
            atomicAdd(&g_done, 1u);
        }
    }
}

// ---------------- inner align (r<12): LDG gathers -> smem -> TMA bulk store ----------------
__device__ void inner_body(const float* __restrict__ x, float* __restrict__ out,
                           int blk, StoreSh& sh) {
    int cblk = blk % CSPLIT_IN;  blk /= CSPLIT_IN;
    int tile = blk % NT_TILES;   blk /= NT_TILES;
    int r    = blk % RES_INNER;
    int b    = blk / RES_INNER;
    const int tid = threadIdx.x;

    const int tsz = (tile < 4) ? 1024 : (DT - 4096);   // 904 on last tile

    int   lo[4], hi[4];
    float wlo[4], whi[4];
    bool  ok[4];

    #pragma unroll
    for (int j = 0; j < 4; ++j) {
        int idx = j * 256 + tid;
        int dt  = tile * 1024 + idx;          // lanes consecutive -> coalesced loads
        ok[j]   = (idx < tsz);
        int dd  = ok[j] ? dt : 0;
        int d   = dd / T;
        int t   = dd - d * T;
        bool va     = (t + d) < T;
        float cl    = (float)(d + 1);
        float start = va ? ((float)t - cl * 0.5f) : 0.0f;
        float end   = va ? ((float)(t + d) + cl * 0.5f) : 0.0f;
        float binw  = __fdiv_rn(end - start, (float)RES_INNER);
        float coord = __fadd_rn(start, __fmul_rn((float)r + 0.5f, binw));
        bool valid  = (coord >= -1.0f) && (coord <= (float)T);
        float lof   = floorf(coord);
        float frac  = coord - lof;
        int loi = (int)lof;
        loi = loi < 0 ? 0 : (loi > T - 1 ? T - 1 : loi);
        int hii = loi + 1 > T - 1 ? T - 1 : loi + 1;
        lo[j] = loi; hi[j] = hii;
        wlo[j] = valid ? (1.0f - frac) : 0.0f;
        whi[j] = valid ? frac : 0.0f;
    }

    const int c0 = cblk * CPB_IN;
    const float* src = x + ((size_t)b * CH + c0) * T;
    float* gbase = out + ((b * CH + c0) * RES_TOT + r) * DT + tile * 1024;
    const uint32_t sbuf0 = smem_u32(&sh.obuf[0][0]);
    const uint32_t bytes = (uint32_t)tsz * 4u;

    #pragma unroll
    for (int c = 0; c < CPB_IN; ++c) {
        const int p = c & 1;
        if (c >= 2) {
            if (tid == 0) bulk_wait_read1();   // buffer p free again
            __syncthreads();
        }
        float* buf = sh.obuf[p];
        #pragma unroll
        for (int j = 0; j < 4; ++j) {
            if (ok[j])
                buf[j * 256 + tid] = fmaf(whi[j], __ldg(src + hi[j]), wlo[j] * __ldg(src + lo[j]));
        }
        __syncthreads();
        if (tid == 0) {
            fence_async_proxy();
            bulk_store(gbase, sbuf0 + (uint32_t)p * 4096u, bytes);
            bulk_commit();
        }
        src += T;
        gbase += OUT_C_STRIDE;
    }
    if (tid == 0) bulk_wait_all();
}

// ---------------- ctx align (r>=12): 3-coeff, smem -> TMA bulk store ----------------
__device__ void ctx_body(float* __restrict__ out, int blk, StoreSh& sh) {
    int cblk = blk % CSPLIT_CTX;  blk /= CSPLIT_CTX;
    int tile = blk % NT_TILES;    blk /= NT_TILES;
    int rr   = blk % RES_CTX;
    int b    = blk / RES_CTX;
    const int tid = threadIdx.x;
    const int c0 = cblk * CPB_CTX;

    // wait for kNN blocks (IDs 0..199 guaranteed resident in wave 1)
    if (tid == 0) {
        while (atomicAdd(&g_done, 0u) < (unsigned)KNN_GRID) { __nanosleep(64); }
        __threadfence();
    }
    __syncthreads();

    // stage this block's 60 ctx values
    if (tid < CPB_CTX * KNN) sh.g[tid] = g_ctx[(b * CH + c0) * KNN + tid];
    __syncthreads();

    const int tsz = (tile < 4) ? 1024 : (DT - 4096);

    float a0[4], a1[4], a2[4];
    bool  ok[4];

    #pragma unroll
    for (int j = 0; j < 4; ++j) {
        int idx = j * 256 + tid;
        int dt  = tile * 1024 + idx;
        ok[j]   = (idx < tsz);
        int dd  = ok[j] ? dt : 0;
        int d   = dd / T;
        int t   = dd - d * T;
        bool va     = (t + d) < T;
        float cl    = (float)(d + 1);
        float start = va ? ((float)t - cl * 0.5f) : 0.0f;
        float end   = va ? ((float)(t + d) + cl * 0.5f) : 0.0f;
        float binw  = (end - start) * 0.0625f;          // /16 exact
        float coord = __fadd_rn(start, __fmul_rn((float)rr + 0.5f, binw));
        bool valid  = (coord >= -1.0f) && (coord <= (float)KNN);
        float lof   = floorf(coord);
        float frac  = coord - lof;
        int loi = (int)lof;
        loi = loi < 0 ? 0 : (loi > KNN - 1 ? KNN - 1 : loi);
        int hii = loi + 1 > KNN - 1 ? KNN - 1 : loi + 1;
        float wlo = valid ? (1.0f - frac) : 0.0f;
        float whi = valid ? frac : 0.0f;
        float t0 = 0.f, t1 = 0.f, t2 = 0.f;
        if (loi == 0) t0 += wlo; else if (loi == 1) t1 += wlo; else t2 += wlo;
        if (hii == 0) t0 += whi; else if (hii == 1) t1 += whi; else t2 += whi;
        a0[j] = t0; a1[j] = t1; a2[j] = t2;
    }

    float* gbase = out + ((b * CH + c0) * RES_TOT + (RES_INNER + rr)) * DT + tile * 1024;
    const uint32_t sbuf0 = smem_u32(&sh.obuf[0][0]);
    const uint32_t bytes = (uint32_t)tsz * 4u;

    #pragma unroll 4
    for (int c = 0; c < CPB_CTX; ++c) {
        const int p = c & 1;
        if (c >= 2) {
            if (tid == 0) bulk_wait_read1();
            __syncthreads();
        }
        float g0 = sh.g[c * KNN + 0], g1 = sh.g[c * KNN + 1], g2 = sh.g[c * KNN + 2];
        float* buf = sh.obuf[p];
        #pragma unroll
        for (int j = 0; j < 4; ++j) {
            if (ok[j])
                buf[j * 256 + tid] = fmaf(a2[j], g2, fmaf(a1[j], g1, a0[j] * g0));
        }
        __syncthreads();
        if (tid == 0) {
            fence_async_proxy();
            bulk_store(gbase, sbuf0 + (uint32_t)p * 4096u, bytes);
            bulk_commit();
        }
        gbase += OUT_C_STRIDE;
    }
    if (tid == 0) bulk_wait_all();

    // last ctx block resets counters for deterministic graph replay
    __syncthreads();
    if (tid == 0) {
        unsigned v = atomicAdd(&g_exit, 1u);
        if (v == (unsigned)(CTX_GRID - 1)) {
            g_done = 0;
            g_exit = 0;
            __threadfence();
        }
    }
}

// ---------------- fused kernel ----------------
__global__ void __launch_bounds__(256)
graph_align_fused(const float* __restrict__ x, float* __restrict__ out) {
    __shared__ Sh sh;
    unsigned bid = blockIdx.x;
    if (bid < KNN_GRID) {
        knn_body(x, (int)bid, sh.k);
    } else if (bid < KNN_GRID + INNER_GRID) {
        inner_body(x, out, (int)(bid - KNN_GRID), sh.s);
    } else {
        ctx_body(out, (int)(bid - KNN_GRID - INNER_GRID), sh.s);
    }
}

extern "C" void kernel_launch(void* const* d_in, const int* in_sizes, int n_in,
                              void* d_out, int out_size) {
    const float* x = (const float*)d_in[0];
    float* out = (float*)d_out;
    graph_align_fused<<<TOTAL_GRID, 256>>>(x, out);
}